// round 1
// baseline (speedup 1.0000x reference)
#include <cuda_runtime.h>

#define H 512
#define O 512
#define E 16
#define N_MAX 32768

#define BM 128
#define BN 128
#define BK 16

// ---------------- device scratch (no allocations allowed) ----------------
__device__ int g_eidx[N_MAX];
__device__ int g_count[E];
__device__ int g_offset[E];
__device__ int g_cursor[E];
__device__ int g_perm[N_MAX];

// ---------------- packed f32x2 helpers (sm_100+ PTX) ----------------
__device__ __forceinline__ void fma2(unsigned long long &d, unsigned long long a,
                                     unsigned long long b) {
    asm("fma.rn.f32x2 %0, %1, %2, %0;" : "+l"(d) : "l"(a), "l"(b));
}
__device__ __forceinline__ float2 unpack2(unsigned long long v) {
    float2 r;
    asm("mov.b64 {%0,%1}, %2;" : "=f"(r.x), "=f"(r.y) : "l"(v));
    return r;
}

// ---------------- stage 0: zero counts ----------------
__global__ void init_kernel() {
    int t = threadIdx.x;
    if (t < E) g_count[t] = 0;
}

// ---------------- stage 1: gate logits + argmax ----------------
__global__ void gate_kernel(const float* __restrict__ x, const float* __restrict__ Wg,
                            const float* __restrict__ bg, int n_tokens) {
    __shared__ float Wgs[E * H];  // 32 KB
    int t = threadIdx.x;
    for (int i = t; i < E * H; i += blockDim.x) Wgs[i] = Wg[i];
    __syncthreads();

    int n = blockIdx.x * blockDim.x + t;
    if (n >= n_tokens) return;
    const float* xr = x + (size_t)n * H;

    float acc[E];
#pragma unroll
    for (int e = 0; e < E; e++) acc[e] = bg[e];

    for (int k = 0; k < H; k += 4) {
        float4 xv = *(const float4*)(xr + k);
#pragma unroll
        for (int e = 0; e < E; e++) {
            float4 w = *(const float4*)(&Wgs[e * H + k]);
            acc[e] += xv.x * w.x + xv.y * w.y + xv.z * w.z + xv.w * w.w;
        }
    }

    // argmax with first-occurrence tie-break (matches jnp.argmax)
    int best = 0;
    float bv = acc[0];
#pragma unroll
    for (int e = 1; e < E; e++)
        if (acc[e] > bv) { bv = acc[e]; best = e; }

    // second best
    int sec = (best == 0) ? 1 : 0;
    float sv = acc[sec];
#pragma unroll
    for (int e = 0; e < E; e++)
        if (e != best && acc[e] > sv) { sv = acc[e]; sec = e; }

    // near-tie: recompute the two candidates in fp64 so our argmax == true argmax
    if (bv - sv < 1e-3f) {
        int ea = min(best, sec), eb = max(best, sec);
        double la = (double)bg[ea], lb = (double)bg[eb];
        for (int k = 0; k < H; k++) {
            double xv = (double)xr[k];
            la += xv * (double)Wgs[ea * H + k];
            lb += xv * (double)Wgs[eb * H + k];
        }
        best = (lb > la) ? eb : ea;  // first-occurrence tie-break: ea wins ties
    }

    g_eidx[n] = best;
    atomicAdd(&g_count[best], 1);
}

// ---------------- stage 2: exclusive scan of 16 counts ----------------
__global__ void scan_kernel() {
    if (threadIdx.x == 0) {
        int s = 0;
        for (int e = 0; e < E; e++) {
            g_offset[e] = s;
            g_cursor[e] = s;
            s += g_count[e];
        }
    }
}

// ---------------- stage 3: scatter token ids into per-expert buckets ----------------
__global__ void scatter_kernel(int n_tokens) {
    int n = blockIdx.x * blockDim.x + threadIdx.x;
    if (n >= n_tokens) return;
    int e = g_eidx[n];
    int slot = atomicAdd(&g_cursor[e], 1);
    g_perm[slot] = n;
}

// ---------------- stage 4: grouped gather-GEMM ----------------
// out[token, n] = sum_k x[token,k] * We[e,n,k] + be[e,n]
// BM=BN=128, BK=16, 256 threads, 8x8 f32x2 micro-tile per thread.
__global__ __launch_bounds__(256, 1) void expert_gemm(const float* __restrict__ x,
                                                      const float* __restrict__ We,
                                                      const float* __restrict__ be,
                                                      float* __restrict__ out) {
    int e = blockIdx.z;
    int cnt = g_count[e];
    int row0 = blockIdx.y * BM;
    if (row0 >= cnt) return;
    int n0 = blockIdx.x * BN;
    int base = g_offset[e];

    // pair layout: element [k2][m] holds (k=2*k2, k=2*k2+1) for row m
    __shared__ __align__(16) float2 As[BK / 2][BM];
    __shared__ __align__(16) float2 Bs[BK / 2][BN];
    __shared__ int rows[BM];

    int t = threadIdx.x;
    if (t < BM) {
        int r = row0 + t;
        rows[t] = (r < cnt) ? g_perm[base + r] : -1;
    }
    __syncthreads();

    const float* Wbase = We + (size_t)e * O * H + (size_t)n0 * H;

    unsigned long long acc[8][8];
#pragma unroll
    for (int i = 0; i < 8; i++)
#pragma unroll
        for (int j = 0; j < 8; j++) acc[i][j] = 0ull;

    int tx = t & 15, ty = t >> 4;

    // loader assignment: idx -> (row = idx/4, k4 = (idx%4)*4), idx in {t, t+256}
    int am[2], ak[2];
#pragma unroll
    for (int u = 0; u < 2; u++) {
        int idx = t + u * 256;
        am[u] = idx >> 2;
        ak[u] = (idx & 3) * 4;
    }

    // prefetch tile kt=0
    float4 pa[2], pb[2];
#pragma unroll
    for (int u = 0; u < 2; u++) {
        int r = rows[am[u]];
        pa[u] = (r >= 0) ? *(const float4*)(x + (size_t)r * H + ak[u])
                         : make_float4(0.f, 0.f, 0.f, 0.f);
        pb[u] = *(const float4*)(Wbase + (size_t)am[u] * H + ak[u]);
    }

    for (int kt = 0; kt < H; kt += BK) {
        __syncthreads();
#pragma unroll
        for (int u = 0; u < 2; u++) {
            As[(ak[u] >> 1)][am[u]]     = make_float2(pa[u].x, pa[u].y);
            As[(ak[u] >> 1) + 1][am[u]] = make_float2(pa[u].z, pa[u].w);
            Bs[(ak[u] >> 1)][am[u]]     = make_float2(pb[u].x, pb[u].y);
            Bs[(ak[u] >> 1) + 1][am[u]] = make_float2(pb[u].z, pb[u].w);
        }
        __syncthreads();

        int ktn = kt + BK;
        if (ktn < H) {
#pragma unroll
            for (int u = 0; u < 2; u++) {
                int r = rows[am[u]];
                pa[u] = (r >= 0) ? *(const float4*)(x + (size_t)r * H + ktn + ak[u])
                                 : make_float4(0.f, 0.f, 0.f, 0.f);
                pb[u] = *(const float4*)(Wbase + (size_t)am[u] * H + ktn + ak[u]);
            }
        }

#pragma unroll
        for (int k2 = 0; k2 < BK / 2; k2++) {
            unsigned long long a[8], b[8];
#pragma unroll
            for (int h = 0; h < 4; h++) {
                // conflict-free LDS.128: consecutive tx/ty read consecutive 16B
                ulonglong2 av = *(const ulonglong2*)&As[k2][h * 32 + ty * 2];
                a[2 * h] = av.x;
                a[2 * h + 1] = av.y;
                ulonglong2 bv = *(const ulonglong2*)&Bs[k2][h * 32 + tx * 2];
                b[2 * h] = bv.x;
                b[2 * h + 1] = bv.y;
            }
#pragma unroll
            for (int i = 0; i < 8; i++)
#pragma unroll
                for (int j = 0; j < 8; j++) fma2(acc[i][j], a[i], b[j]);
        }
    }

    // epilogue: acc.x (even-k sum) + acc.y (odd-k sum) + bias, scatter to token rows
#pragma unroll
    for (int i = 0; i < 8; i++) {
        int m = (i >> 1) * 32 + ty * 2 + (i & 1);
        int r = rows[m];
        if (r < 0) continue;
        float* orow = out + (size_t)r * O + n0;
        const float* brow = be + e * O + n0;
#pragma unroll
        for (int j2 = 0; j2 < 4; j2++) {
            int n = j2 * 32 + tx * 2;
            float2 bias = *(const float2*)(brow + n);
            float2 lo = unpack2(acc[i][2 * j2]);
            float2 hi = unpack2(acc[i][2 * j2 + 1]);
            float2 o;
            o.x = lo.x + lo.y + bias.x;
            o.y = hi.x + hi.y + bias.y;
            *(float2*)(orow + n) = o;
        }
    }
}

// ---------------- launch ----------------
extern "C" void kernel_launch(void* const* d_in, const int* in_sizes, int n_in,
                              void* d_out, int out_size) {
    const float* x  = (const float*)d_in[0];  // [N, H]
    const float* Wg = (const float*)d_in[1];  // [E, H]
    const float* bg = (const float*)d_in[2];  // [E]
    const float* We = (const float*)d_in[3];  // [E, O, H]
    const float* be = (const float*)d_in[4];  // [E, O]
    float* out = (float*)d_out;               // [N, O]

    int n_tokens = in_sizes[0] / H;

    init_kernel<<<1, 32>>>();
    gate_kernel<<<(n_tokens + 255) / 256, 256>>>(x, Wg, bg, n_tokens);
    scan_kernel<<<1, 32>>>();
    scatter_kernel<<<(n_tokens + 255) / 256, 256>>>(n_tokens);

    int mtiles = (n_tokens + BM - 1) / BM;  // worst case: all tokens on one expert
    dim3 grid(O / BN, mtiles, E);
    expert_gemm<<<grid, 256>>>(x, We, be, out);
}

// round 4
// speedup vs baseline: 2.0888x; 2.0888x over previous
#include <cuda_runtime.h>
#include <cuda_bf16.h>
#include <cstdint>

#define H 512
#define O 512
#define E 16
#define N_MAX 32768

#define BM 128          // tokens per CTA tile
#define BN 128          // outputs per CTA tile
#define BKT 64          // bf16 k-elements per smem tile
#define KTILES (H / BKT)
#define MAX_TILES 272   // worst case: one 256-tile expert + 15 singletons

// ---------------- device scratch ----------------
__device__ int g_eidx[N_MAX];
__device__ int g_count[E];
__device__ int g_offset[E];
__device__ int g_cursor[E];
__device__ int g_perm[N_MAX];
__device__ int g_tile_e[MAX_TILES];
__device__ int g_tile_m0[MAX_TILES];
__device__ int g_ntiles;

// ---------------- helpers ----------------
__device__ __forceinline__ uint32_t smem_u32(const void* p) {
    uint32_t a;
    asm("{ .reg .u64 t; cvta.to.shared.u64 t, %1; cvt.u32.u64 %0, t; }" : "=r"(a) : "l"(p));
    return a;
}
#define SWZ(o) ((o) ^ (((o) >> 3) & 0x70))

// fp32 pair -> bf16 hi pair + bf16 lo (residual) pair. low 16 bits = first elem.
__device__ __forceinline__ void cvt_split(float a, float b, uint32_t& hi, uint32_t& lo) {
    asm("cvt.rn.satfinite.bf16x2.f32 %0, %1, %2;" : "=r"(hi) : "f"(b), "f"(a));
    float ha = __uint_as_float(hi << 16);
    float hb = __uint_as_float(hi & 0xffff0000u);
    float ra = a - ha, rb = b - hb;
    asm("cvt.rn.satfinite.bf16x2.f32 %0, %1, %2;" : "=r"(lo) : "f"(rb), "f"(ra));
}

__device__ __forceinline__ void ldsm4(uint32_t* r, uint32_t addr) {
    asm volatile("ldmatrix.sync.aligned.m8n8.x4.shared.b16 {%0,%1,%2,%3}, [%4];"
                 : "=r"(r[0]), "=r"(r[1]), "=r"(r[2]), "=r"(r[3]) : "r"(addr));
}

__device__ __forceinline__ void mma_bf16(float* d, const uint32_t* a, const uint32_t* b) {
    asm volatile(
        "mma.sync.aligned.m16n8k16.row.col.f32.bf16.bf16.f32 "
        "{%0,%1,%2,%3}, {%4,%5,%6,%7}, {%8,%9}, {%0,%1,%2,%3};"
        : "+f"(d[0]), "+f"(d[1]), "+f"(d[2]), "+f"(d[3])
        : "r"(a[0]), "r"(a[1]), "r"(a[2]), "r"(a[3]), "r"(b[0]), "r"(b[1]));
}

// ---------------- smem layout ----------------
// [0,512)    rows[128]
// [512,1024) bias[128]
// [1024, +2*65536) double buffer: per buf {A_hi 16K, A_lo 16K, B_hi 16K, B_lo 16K}
#define BUF_SZ 65536
#define A_HI 0
#define A_LO 16384
#define B_HI 32768
#define B_LO 49152
#define SMEM_TOTAL (1024 + 2 * BUF_SZ)

// ---------------- stage 0 ----------------
__global__ void init_kernel() {
    int t = threadIdx.x;
    if (t < E) g_count[t] = 0;
}

// ---------------- stage 1: gate (known-correct) ----------------
__global__ void gate_kernel(const float* __restrict__ x, const float* __restrict__ Wg,
                            const float* __restrict__ bg, int n_tokens) {
    __shared__ float Wgs[E * H];
    int t = threadIdx.x;
    for (int i = t; i < E * H; i += blockDim.x) Wgs[i] = Wg[i];
    __syncthreads();

    int n = blockIdx.x * blockDim.x + t;
    if (n >= n_tokens) return;
    const float* xr = x + (size_t)n * H;

    float acc[E];
#pragma unroll
    for (int e = 0; e < E; e++) acc[e] = bg[e];

    for (int k = 0; k < H; k += 4) {
        float4 xv = *(const float4*)(xr + k);
#pragma unroll
        for (int e = 0; e < E; e++) {
            float4 w = *(const float4*)(&Wgs[e * H + k]);
            acc[e] += xv.x * w.x + xv.y * w.y + xv.z * w.z + xv.w * w.w;
        }
    }

    int best = 0;
    float bv = acc[0];
#pragma unroll
    for (int e = 1; e < E; e++)
        if (acc[e] > bv) { bv = acc[e]; best = e; }

    int sec = (best == 0) ? 1 : 0;
    float sv = acc[sec];
#pragma unroll
    for (int e = 0; e < E; e++)
        if (e != best && acc[e] > sv) { sv = acc[e]; sec = e; }

    if (bv - sv < 1e-3f) {
        int ea = min(best, sec), eb = max(best, sec);
        double la = (double)bg[ea], lb = (double)bg[eb];
        for (int k = 0; k < H; k++) {
            double xv = (double)xr[k];
            la += xv * (double)Wgs[ea * H + k];
            lb += xv * (double)Wgs[eb * H + k];
        }
        best = (lb > la) ? eb : ea;  // first-occurrence tie-break
    }

    g_eidx[n] = best;
    atomicAdd(&g_count[best], 1);
}

// ---------------- stage 2: scan + tile table ----------------
__global__ void scan_kernel() {
    if (threadIdx.x != 0) return;
    int s = 0, tc = 0;
    for (int e = 0; e < E; e++) {
        g_offset[e] = s;
        g_cursor[e] = s;
        int c = g_count[e];
        s += c;
        for (int m0 = 0; m0 < c; m0 += BM) {
            g_tile_e[tc] = e;
            g_tile_m0[tc] = m0;
            tc++;
        }
    }
    g_ntiles = tc;
}

// ---------------- stage 3: scatter ----------------
__global__ void scatter_kernel(int n_tokens) {
    int n = blockIdx.x * blockDim.x + threadIdx.x;
    if (n >= n_tokens) return;
    int e = g_eidx[n];
    int slot = atomicAdd(&g_cursor[e], 1);
    g_perm[slot] = n;
}

// ---------------- stage 4: HMMA gather-GEMM (3-term bf16 split) ----------------
__global__ __launch_bounds__(256, 1) void expert_gemm(const float* __restrict__ x,
                                                      const float* __restrict__ We,
                                                      const float* __restrict__ be,
                                                      float* __restrict__ out) {
    int tile = blockIdx.y;
    if (tile >= g_ntiles) return;
    int t = threadIdx.x;
    int e = g_tile_e[tile];
    int m0 = g_tile_m0[tile];
    int cnt = g_count[e];
    int base = g_offset[e];
    int n0 = blockIdx.x * BN;

    extern __shared__ char smem[];
    int* rows = (int*)smem;
    float* bias_s = (float*)(smem + 512);
    uint32_t sb = smem_u32(smem);

    if (t < BM) {
        int m = m0 + t;
        rows[t] = (m < cnt) ? g_perm[base + m] : -1;
        bias_s[t] = be[e * O + n0 + t];
    }
    __syncthreads();

    // ---- loader precompute: thread t handles rows {t/16 + 16g}, k4 = t%16 ----
    int baseRow = t >> 4;
    int k4 = t & 15;
    const float* Wb = We + (size_t)e * O * H + (size_t)n0 * H + k4 * 4;
    int rA[8];
    const float* pA[8];
    const float* pB[8];
    uint32_t swo[8];
#pragma unroll
    for (int g = 0; g < 8; g++) {
        int row = baseRow + g * 16;
        int r = rows[row];
        rA[g] = r;
        pA[g] = x + (size_t)(r < 0 ? 0 : r) * H + k4 * 4;
        pB[g] = Wb + (size_t)row * H;   // FIX: B row = baseRow + g*16 (was g*16)
        swo[g] = SWZ((uint32_t)(row * 128 + k4 * 8));
    }

    // prefetch kt=0
    float4 pa[8], pb[8];
#pragma unroll
    for (int g = 0; g < 8; g++) {
        pa[g] = (rA[g] >= 0) ? *(const float4*)(pA[g]) : make_float4(0.f, 0.f, 0.f, 0.f);
        pb[g] = *(const float4*)(pB[g]);
    }

    // ---- warp tiling: 8 warps = 4m x 2n, warp tile 32x64 ----
    int w = t >> 5, lane = t & 31;
    int warpM = w & 3, warpN = w >> 2;
    int grp = lane >> 3, lr = lane & 7;
    int arow = lr + (grp & 1) * 8;   // A ldmatrix row-in-frag
    int akc = (grp >> 1) * 8;        // A ldmatrix k offset
    int brow = (grp >> 1) * 8 + lr;  // B ldmatrix n-row-in-frag
    int bkc = (grp & 1) * 8;         // B ldmatrix k offset

    float acc[2][8][4];
#pragma unroll
    for (int i = 0; i < 2; i++)
#pragma unroll
        for (int j = 0; j < 8; j++)
#pragma unroll
            for (int c = 0; c < 4; c++) acc[i][j][c] = 0.f;

    for (int kt = 0; kt < KTILES; kt++) {
        int b = kt & 1;
        char* buf = smem + 1024 + b * BUF_SZ;
        __syncthreads();  // buffer b free

        // convert + store fp32 prefetch regs -> bf16 hi/lo smem tiles
#pragma unroll
        for (int g = 0; g < 8; g++) {
            uint32_t h01, l01, h23, l23;
            cvt_split(pa[g].x, pa[g].y, h01, l01);
            cvt_split(pa[g].z, pa[g].w, h23, l23);
            *(uint2*)(buf + A_HI + swo[g]) = make_uint2(h01, h23);
            *(uint2*)(buf + A_LO + swo[g]) = make_uint2(l01, l23);
            cvt_split(pb[g].x, pb[g].y, h01, l01);
            cvt_split(pb[g].z, pb[g].w, h23, l23);
            *(uint2*)(buf + B_HI + swo[g]) = make_uint2(h01, h23);
            *(uint2*)(buf + B_LO + swo[g]) = make_uint2(l01, l23);
        }
        __syncthreads();  // buffer b ready

        // issue next tile's global loads (overlap with MMA below)
        if (kt + 1 < KTILES) {
            int off = (kt + 1) * BKT;
#pragma unroll
            for (int g = 0; g < 8; g++) {
                pa[g] = (rA[g] >= 0) ? *(const float4*)(pA[g] + off)
                                     : make_float4(0.f, 0.f, 0.f, 0.f);
                pb[g] = *(const float4*)(pB[g] + off);
            }
        }

        uint32_t bufb = sb + 1024 + b * BUF_SZ;
#pragma unroll
        for (int ks = 0; ks < 4; ks++) {
            uint32_t ah[2][4], al[2][4], bh[4][4], bl[4][4];
#pragma unroll
            for (int mi = 0; mi < 2; mi++) {
                uint32_t off = SWZ((uint32_t)((warpM * 32 + mi * 16 + arow) * 128 +
                                              (ks * 16 + akc) * 2));
                ldsm4(ah[mi], bufb + A_HI + off);
                ldsm4(al[mi], bufb + A_LO + off);
            }
#pragma unroll
            for (int njp = 0; njp < 4; njp++) {
                uint32_t off = SWZ((uint32_t)((warpN * 64 + njp * 16 + brow) * 128 +
                                              (ks * 16 + bkc) * 2));
                ldsm4(bh[njp], bufb + B_HI + off);
                ldsm4(bl[njp], bufb + B_LO + off);
            }
#pragma unroll
            for (int mi = 0; mi < 2; mi++)
#pragma unroll
                for (int njp = 0; njp < 4; njp++) {
                    mma_bf16(acc[mi][njp * 2],     ah[mi], &bh[njp][0]);
                    mma_bf16(acc[mi][njp * 2 + 1], ah[mi], &bh[njp][2]);
                    mma_bf16(acc[mi][njp * 2],     ah[mi], &bl[njp][0]);
                    mma_bf16(acc[mi][njp * 2 + 1], ah[mi], &bl[njp][2]);
                    mma_bf16(acc[mi][njp * 2],     al[mi], &bh[njp][0]);
                    mma_bf16(acc[mi][njp * 2 + 1], al[mi], &bh[njp][2]);
                }
        }
    }

    // ---- epilogue: acc + bias -> gathered token rows ----
    int qrow = lane >> 2, qcol = lane & 3;
#pragma unroll
    for (int mi = 0; mi < 2; mi++)
#pragma unroll
        for (int h = 0; h < 2; h++) {
            int m = warpM * 32 + mi * 16 + h * 8 + qrow;
            int r = rows[m];
            if (r < 0) continue;
            float* orow = out + (size_t)r * O + n0 + warpN * 64;
#pragma unroll
            for (int nj = 0; nj < 8; nj++) {
                int col = nj * 8 + qcol * 2;
                float2 o;
                o.x = acc[mi][nj][h * 2]     + bias_s[warpN * 64 + col];
                o.y = acc[mi][nj][h * 2 + 1] + bias_s[warpN * 64 + col + 1];
                *(float2*)(orow + col) = o;
            }
        }
}

// ---------------- launch ----------------
extern "C" void kernel_launch(void* const* d_in, const int* in_sizes, int n_in,
                              void* d_out, int out_size) {
    const float* x  = (const float*)d_in[0];  // [N, H]
    const float* Wg = (const float*)d_in[1];  // [E, H]
    const float* bg = (const float*)d_in[2];  // [E]
    const float* We = (const float*)d_in[3];  // [E, O, H]
    const float* be = (const float*)d_in[4];  // [E, O]
    float* out = (float*)d_out;               // [N, O]

    int n_tokens = in_sizes[0] / H;

    cudaFuncSetAttribute(expert_gemm, cudaFuncAttributeMaxDynamicSharedMemorySize,
                         SMEM_TOTAL);

    init_kernel<<<1, 32>>>();
    gate_kernel<<<(n_tokens + 255) / 256, 256>>>(x, Wg, bg, n_tokens);
    scan_kernel<<<1, 32>>>();
    scatter_kernel<<<(n_tokens + 255) / 256, 256>>>(n_tokens);

    dim3 grid(O / BN, MAX_TILES);
    expert_gemm<<<grid, 256, SMEM_TOTAL>>>(x, We, be, out);
}